// round 12
// baseline (speedup 1.0000x reference)
#include <cuda_runtime.h>
#include <cstdint>

#define BB 64
#define NN 2048
#define MM 256
#define CHUNKS 32                        // partial chunks per batch
#define ROWS_PER_BLOCK (NN / CHUNKS)     // 64 rows per block

// ---- scratch (static __device__ globals; no allocation) ----
__device__ float  g_partial[CHUNKS * BB * MM];   // chunk-major partials, 2 MB
__device__ float2 g_scal[CHUNKS * BB];           // (sum u, sum u*ww) per chunk
__device__ int    g_count[BB];                   // arrival counters (self-resetting)

// ---- cp.async helpers ----
__device__ __forceinline__ void cp_async16(uint32_t smem_dst, const void* gmem_src) {
    asm volatile("cp.async.cg.shared.global [%0], [%1], 16;\n"
                 :: "r"(smem_dst), "l"(gmem_src));
}
__device__ __forceinline__ void cp_commit() {
    asm volatile("cp.async.commit_group;\n");
}
template <int N>
__device__ __forceinline__ void cp_wait() {
    asm volatile("cp.async.wait_group %0;\n" :: "n"(N));
}

// ============================================================================
// Single kernel: streaming pass over memory (read ONCE) + fenced tail reduce.
//
// OCCUPANCY-FIRST redesign (R11 showed we were resource-capped at 32 warps):
//   - cp.async single-row ring (2 x 1KB per warp): data bypasses registers
//   - one row per iteration; row data extracted to regs once, reused for
//     dot AND accumulate; refill issued immediately after extraction
//   - __launch_bounds__(256, 6): 42-reg cap, ~22KB smem -> 48 warps/SM (75%)
// Cross-warp parallelism covers the per-row shuffle/exp chain (k_pass1 proved
// 6.7 TB/s with this shape). Epilogue: publish partial; 32nd-arriving block
// per batch does a fixed-order deterministic reduce and writes out.
// grid = BB*CHUNKS = 2048 blocks, block = 256 (8 warps x 8 rows each).
// ============================================================================
__global__ void __launch_bounds__(256, 6)
k_fused(const float* __restrict__ mem, const float* __restrict__ k,
        const float* __restrict__ g,   const float* __restrict__ w_prev,
        const int* __restrict__ w_lu_prev, float* __restrict__ out)
{
    const int bid   = blockIdx.x;
    const int b     = bid >> 5;          // / CHUNKS
    const int chunk = bid & (CHUNKS - 1);
    const int row0  = chunk * ROWS_PER_BLOCK;
    const int t     = threadIdx.x;
    const int warp  = t >> 5, lane = t & 31;

    __shared__ float4 s_ring[8][2][MM / 4];      // warp x buf x 1 row, 16 KB
    __shared__ float4 sk4[MM / 4];               // k[b,:]                1 KB
    __shared__ float  s_mask[ROWS_PER_BLOCK];
    __shared__ float  s_ww[ROWS_PER_BLOCK];
    __shared__ float  s_red[8];
    __shared__ float  s_kinv;

    // ---- prologue: k into smem + ||k||, per-row mask/ww ----
    if (t < MM / 4) sk4[t] = reinterpret_cast<const float4*>(k + (size_t)b * MM)[t];
    float kv = k[(size_t)b * MM + t];
    float ks = kv * kv;
    #pragma unroll
    for (int off = 16; off > 0; off >>= 1) ks += __shfl_down_sync(0xffffffffu, ks, off);
    if (lane == 0) s_red[warp] = ks;

    const float gb = g[b];
    if (t < ROWS_PER_BLOCK) {
        int n = row0 + t;
        float wlu = (float)w_lu_prev[(size_t)b * NN + n];
        float wrp = w_prev[((size_t)b * 2 + 1) * NN + n];    // w_prev[:,1,:]
        s_mask[t] = 1.f - wlu;
        s_ww[t]   = gb * wrp + (1.f - gb) * wlu;
    }
    __syncthreads();
    if (t == 0) {
        float r = s_red[0];
        #pragma unroll
        for (int i = 1; i < 8; i++) r += s_red[i];
        s_kinv = 1.f / fmaxf(sqrtf(r), 1e-8f);
    }
    __syncthreads();

    const float  kinv = s_kinv;
    const float4 k0 = sk4[lane], k1 = sk4[lane + 32];
    const float4* gwarp = reinterpret_cast<const float4*>(
        mem + ((size_t)b * NN + row0 + warp * 8) * MM);   // this warp's 8 rows

    const uint32_t ring =
        (uint32_t)__cvta_generic_to_shared(&s_ring[warp][0][0]);

    float4 acc0 = make_float4(0.f, 0.f, 0.f, 0.f);
    float4 acc1 = make_float4(0.f, 0.f, 0.f, 0.f);
    float  U = 0.f, W = 0.f;

    // ---- pipeline prolog: rows 0 and 1 into the two ring buffers ----
    #pragma unroll
    for (int r = 0; r < 2; r++) {
        cp_async16(ring + (uint32_t)(r * 64 + lane)      * 16, gwarp + r * 64 + lane);
        cp_async16(ring + (uint32_t)(r * 64 + lane + 32) * 16, gwarp + r * 64 + lane + 32);
        cp_commit();
    }

    // ---- main loop: 8 rows, depth-2 single-row ring ----
    #pragma unroll
    for (int p = 0; p < 8; p++) {
        if (p < 7) cp_wait<1>(); else cp_wait<0>();
        __syncwarp();
        const float4* tb = s_ring[warp][p & 1];
        float4 v0 = tb[lane];
        float4 v1 = tb[lane + 32];
        __syncwarp();                        // all lanes extracted -> buf free

        // refill this buffer with row p+2 (overlaps the compute below)
        if (p < 6) {
            const int buf = p & 1;
            cp_async16(ring + (uint32_t)(buf * 64 + lane)      * 16,
                       gwarp + (p + 2) * 64 + lane);
            cp_async16(ring + (uint32_t)(buf * 64 + lane + 32) * 16,
                       gwarp + (p + 2) * 64 + lane + 32);
            cp_commit();
        }

        float dot = v0.x * k0.x + v0.y * k0.y + v0.z * k0.z + v0.w * k0.w
                  + v1.x * k1.x + v1.y * k1.y + v1.z * k1.z + v1.w * k1.w;
        float ss  = v0.x * v0.x + v0.y * v0.y + v0.z * v0.z + v0.w * v0.w
                  + v1.x * v1.x + v1.y * v1.y + v1.z * v1.z + v1.w * v1.w;
        #pragma unroll
        for (int off = 16; off > 0; off >>= 1) {
            dot += __shfl_xor_sync(0xffffffffu, dot, off);
            ss  += __shfl_xor_sync(0xffffffffu, ss,  off);
        }

        const int rl = warp * 8 + p;
        float u = __expf(dot * kinv * rsqrtf(fmaxf(ss, 1e-16f)));
        float c = u * s_mask[rl];
        acc0.x += c * v0.x; acc0.y += c * v0.y;
        acc0.z += c * v0.z; acc0.w += c * v0.w;
        acc1.x += c * v1.x; acc1.y += c * v1.y;
        acc1.z += c * v1.z; acc1.w += c * v1.w;
        if (lane == 0) { U += u; W += u * s_ww[rl]; }
    }

    // ---- block epilogue: reduce 8 warp accumulators, publish partial ----
    __shared__ float4 red0[8][32];
    __shared__ float4 red1[8][32];
    __shared__ float  sU[8], sW[8];
    red0[warp][lane] = acc0;
    red1[warp][lane] = acc1;
    if (lane == 0) { sU[warp] = U; sW[warp] = W; }
    __syncthreads();

    if (t < 64) {
        float4 s = make_float4(0.f, 0.f, 0.f, 0.f);
        #pragma unroll
        for (int w = 0; w < 8; w++) {
            float4 a = (t < 32) ? red0[w][t] : red1[w][t - 32];
            s.x += a.x; s.y += a.y; s.z += a.z; s.w += a.w;
        }
        reinterpret_cast<float4*>(
            g_partial + ((size_t)chunk * BB + b) * MM)[t] = s;
    }
    if (t == 0) {
        float Ut = sU[0], Wt = sW[0];
        #pragma unroll
        for (int w = 1; w < 8; w++) { Ut += sU[w]; Wt += sW[w]; }
        g_scal[(size_t)chunk * BB + b] = make_float2(Ut, Wt);
    }

    // ---- fenced tail reduce: 32nd-arriving block per batch finishes b ----
    __shared__ int s_last;
    __threadfence();                 // make this block's partial globally visible
    __syncthreads();                 // partial writes done before counting
    if (t == 0) s_last = (atomicAdd(&g_count[b], 1) == CHUNKS - 1) ? 1 : 0;
    __syncthreads();
    if (!s_last) return;

    __threadfence();                 // see all other blocks' partials

    // 256 threads, one output column each; fixed-order sum -> deterministic
    float acc = 0.f;
    #pragma unroll
    for (int c = 0; c < CHUNKS; c++)
        acc += g_partial[((size_t)c * BB + b) * MM + t];

    __shared__ float s_Ut, s_Wt;
    if (t < 32) {
        float2 sc = g_scal[(size_t)t * BB + b];
        float u = sc.x, w = sc.y;
        #pragma unroll
        for (int off = 16; off > 0; off >>= 1) {
            u += __shfl_down_sync(0xffffffffu, u, off);
            w += __shfl_down_sync(0xffffffffu, w, off);
        }
        if (t == 0) { s_Ut = u; s_Wt = w; g_count[b] = 0; }   // reset for replay
    }
    __syncthreads();

    out[(size_t)b * MM + t] = (acc + s_Wt * k[(size_t)b * MM + t]) / s_Ut;
}

// ============================================================================
extern "C" void kernel_launch(void* const* d_in, const int* in_sizes, int n_in,
                              void* d_out, int out_size)
{
    const float* mem       = (const float*)d_in[0];   // (64,2048,256) f32
    const float* k         = (const float*)d_in[1];   // (64,256) f32
    const float* g         = (const float*)d_in[2];   // (64,1) f32
    // d_in[3] gamma: unused (dead w.r.t. output)
    const float* w_prev    = (const float*)d_in[4];   // (64,2,2048) f32
    const int*   w_lu_prev = (const int*)d_in[5];     // (64,2048) i32
    // d_in[6] n: unused (sort/w_lu are dead w.r.t. output)
    float* out = (float*)d_out;                       // (64,256) f32

    k_fused<<<BB * CHUNKS, 256>>>(mem, k, g, w_prev, w_lu_prev, out);
}